// round 14
// baseline (speedup 1.0000x reference)
#include <cuda_runtime.h>
#include <cuda_bf16.h>
#include <cstdint>
#include <math.h>

#define BB 64
#define NN 512
#define EE 8192
#define HH 128
#define MM (BB*NN)   // 32768
#define MM2 (2*MM)

// ---------------- scratch (static device allocations) ----------------
__device__ float g_X1 [(size_t)MM2*128];
__device__ float g_Hb [(size_t)MM2*128];
__device__ float g_pos[(size_t)MM*128];
__device__ float g_dinv [3*MM];
__device__ int   g_offs [3*BB*(NN+1)];
__device__ int   g_ssrc [3*BB*EE];
__device__ float g_snorm[3*BB*EE];
__device__ float g_roots[3*BB*HH];       // slots 1,2 used (mal); pos read direct
__device__ float g_bfuse[128];           // fe_b2 @ g1_W
__device__ int   g_midxA[MM2];           // mal: global row into g_pos
__device__ int   g_midxB[MM2];           // mal: global row into features
// pre-split, pre-transposed weights: fe1 @0 (64K), fused @65536 (32K), g2 @98304 (32K)
__device__ unsigned short g_wt[131072];

// ---------------- bf16 helpers ----------------
__device__ __forceinline__ unsigned short bfh(float x) {
    return __bfloat16_as_ushort(__float2bfloat16(x));
}

// mma.sync m16n8k16 row.col f32.bf16.bf16.f32, D += A*B
__device__ __forceinline__ void mma16816(float* d, const uint32_t* a, uint32_t b0, uint32_t b1) {
    asm volatile(
        "mma.sync.aligned.m16n8k16.row.col.f32.bf16.bf16.f32 "
        "{%0,%1,%2,%3}, {%4,%5,%6,%7}, {%8,%9}, {%0,%1,%2,%3};"
        : "+f"(d[0]), "+f"(d[1]), "+f"(d[2]), "+f"(d[3])
        : "r"(a[0]), "r"(a[1]), "r"(a[2]), "r"(a[3]), "r"(b0), "r"(b1));
}

__device__ __forceinline__ void prefetchL2(const void* p) {
    asm volatile("prefetch.global.L2 [%0];" :: "l"(p));
}

// ---------------- combined weight prep (fused weight computed inline) ----------------
__global__ void wprep_all_kernel(const float* __restrict__ fe_W1,
                                 const float* __restrict__ W2, const float* __restrict__ b2,
                                 const float* __restrict__ G1,
                                 const float* __restrict__ g2W) {
    int bid = blockIdx.x;
    int t = threadIdx.x;
    unsigned short* dst;
    int K, idx;
    float x;
    if (bid < 128) {
        dst = g_wt; K = 256; idx = bid*256 + t;
        int k = idx >> 7, n = idx & 127;
        x = fe_W1[(size_t)k * 128 + n];
    } else if (bid < 192) {
        dst = g_wt + 65536; K = 128; idx = (bid-128)*256 + t;
        int k = idx >> 7, n = idx & 127;
        float acc = 0.0f;
        #pragma unroll 8
        for (int m = 0; m < 128; m++) acc += W2[k*128 + m] * G1[m*128 + n];
        x = acc;
        if (bid == 128 && t < 128) {
            float bacc = 0.0f;
            #pragma unroll 8
            for (int m = 0; m < 128; m++) bacc += b2[m] * G1[m*128 + t];
            g_bfuse[t] = bacc;
        }
    } else {
        dst = g_wt + 98304; K = 128; idx = (bid-192)*256 + t;
        int k = idx >> 7, n = idx & 127;
        x = g2W[(size_t)k * 128 + n];
    }
    int k = idx >> 7;
    int n = idx & 127;
    __nv_bfloat16 bh = __float2bfloat16(x);
    float rem = x - __bfloat162float(bh);
    dst[(size_t)n * K + k] = __bfloat16_as_ushort(bh);
    dst[(size_t)128 * K + (size_t)n * K + k] = bfh(rem);
}

// ---------------- mal index flatten ----------------
__global__ void midx_kernel(const int* __restrict__ posidx1, const int* __restrict__ nodes1,
                            const int* __restrict__ posidx2, const int* __restrict__ nodes2) {
    int t = blockIdx.x * 256 + threadIdx.x;
    if (t >= MM2) return;
    int half = t >= MM;
    int r = t & (MM-1);
    int b = r >> 9;
    g_midxA[t] = b * NN + (half ? posidx2[r] : posidx1[r]);
    g_midxB[t] = half ? nodes2[r] : nodes1[r];
}

// ======== GEMM core (M=64 x N=128 tile, 8 warps 2m x 4n, warp tile 32x32) ========
// smem: sAh @0 (9216), sAl @9216, sBh @18432 (18432), sBl @36864 -> 55296 B

#define GEMM_DECLS \
    extern __shared__ char smem[]; \
    char* sAh = smem; \
    char* sAl = smem + 9216; \
    char* sBh = smem + 18432; \
    char* sBl = smem + 36864; \
    int tid  = threadIdx.x; \
    int lane = tid & 31; \
    int wid  = tid >> 5; \
    int row0 = blockIdx.x * 64; \
    int mrow0 = (wid & 1) * 32; \
    int ncol0 = (wid >> 1) * 32; \
    int tq = lane >> 2; \
    int tr = lane & 3; \
    float acc[2][4][4]; \
    _Pragma("unroll") \
    for (int mt = 0; mt < 2; mt++) \
        _Pragma("unroll") \
        for (int nt = 0; nt < 4; nt++) \
            _Pragma("unroll") \
            for (int i = 0; i < 4; i++) acc[mt][nt][i] = 0.0f;

__device__ __forceinline__ void split_store(float4 v, char* sAh, char* sAl, int off) {
    unsigned short h0 = bfh(v.x), h1 = bfh(v.y), h2 = bfh(v.z), h3 = bfh(v.w);
    float l0 = v.x - __bfloat162float(__ushort_as_bfloat16(h0));
    float l1 = v.y - __bfloat162float(__ushort_as_bfloat16(h1));
    float l2 = v.z - __bfloat162float(__ushort_as_bfloat16(h2));
    float l3 = v.w - __bfloat162float(__ushort_as_bfloat16(h3));
    uint2 hv = make_uint2((uint32_t)h0 | ((uint32_t)h1 << 16),
                          (uint32_t)h2 | ((uint32_t)h3 << 16));
    uint2 lv = make_uint2((uint32_t)bfh(l0) | ((uint32_t)bfh(l1) << 16),
                          (uint32_t)bfh(l2) | ((uint32_t)bfh(l3) << 16));
    *(uint2*)(sAh + off) = hv;
    *(uint2*)(sAl + off) = lv;
}

__device__ __forceinline__ void load_B_chunk(const unsigned short* WH, const unsigned short* WL,
                                             int K, int k0, char* sBh, char* sBl, int tid) {
    #pragma unroll
    for (int i = 0; i < 4; i++) {
        int idx = tid + (i << 8);
        int n = idx >> 3;
        int q = idx & 7;
        size_t goff = (size_t)n * K + k0 + q * 8;
        *(uint4*)(sBh + n * 144 + q * 16) = *(const uint4*)(WH + goff);
        *(uint4*)(sBl + n * 144 + q * 16) = *(const uint4*)(WL + goff);
    }
}

// A loader for 64 rows x 64 k: 1024 float4 / 256 threads = 4 iters
__device__ __forceinline__ void load_A_chunk(const float* A, int row0, int K, int k0,
                                             char* sAh, char* sAl, int tid) {
    #pragma unroll
    for (int i = 0; i < 4; i++) {
        int idx = tid + (i << 8);
        int r = idx >> 4;
        int q = idx & 15;
        float4 v = *(const float4*)(A + (size_t)(row0 + r) * K + k0 + q * 4);
        split_store(v, sAh, sAl, r * 144 + q * 8);
    }
}

__device__ __forceinline__ void compute_chunk(char* sAh, char* sAl, char* sBh, char* sBl,
                                              int mrow0, int ncol0, int tq, int tr,
                                              float acc[2][4][4]) {
    #pragma unroll
    for (int ks = 0; ks < 4; ks++) {
        uint32_t ah[2][4], al[2][4];
        #pragma unroll
        for (int mt = 0; mt < 2; mt++) {
            int base = (mrow0 + mt * 16 + tq) * 144 + ks * 32 + tr * 4;
            ah[mt][0] = *(const uint32_t*)(sAh + base);
            ah[mt][1] = *(const uint32_t*)(sAh + base + 1152);
            ah[mt][2] = *(const uint32_t*)(sAh + base + 16);
            ah[mt][3] = *(const uint32_t*)(sAh + base + 1168);
            al[mt][0] = *(const uint32_t*)(sAl + base);
            al[mt][1] = *(const uint32_t*)(sAl + base + 1152);
            al[mt][2] = *(const uint32_t*)(sAl + base + 16);
            al[mt][3] = *(const uint32_t*)(sAl + base + 1168);
        }
        #pragma unroll
        for (int nt = 0; nt < 4; nt++) {
            int bbase = (ncol0 + nt * 8 + tq) * 144 + ks * 32 + tr * 4;
            uint32_t bh0 = *(const uint32_t*)(sBh + bbase);
            uint32_t bh1 = *(const uint32_t*)(sBh + bbase + 16);
            uint32_t bl0 = *(const uint32_t*)(sBl + bbase);
            uint32_t bl1 = *(const uint32_t*)(sBl + bbase + 16);
            #pragma unroll
            for (int mt = 0; mt < 2; mt++) {
                mma16816(acc[mt][nt], ah[mt], bh0, bh1);
                mma16816(acc[mt][nt], al[mt], bh0, bh1);
                mma16816(acc[mt][nt], ah[mt], bl0, bl1);
            }
        }
    }
}

__device__ __forceinline__ void gemm_epilogue(float acc[2][4][4], const float* bias,
                                              float* C, int row0, int mrow0, int ncol0,
                                              int tq, int tr, int act) {
    #pragma unroll
    for (int nt = 0; nt < 4; nt++) {
        int col = ncol0 + nt * 8 + tr * 2;
        float2 bb = make_float2(0.0f, 0.0f);
        if (bias) bb = *(const float2*)(bias + col);
        #pragma unroll
        for (int mt = 0; mt < 2; mt++) {
            int r0 = row0 + mrow0 + mt * 16 + tq;
            float2 v0 = make_float2(acc[mt][nt][0] + bb.x, acc[mt][nt][1] + bb.y);
            float2 v1 = make_float2(acc[mt][nt][2] + bb.x, acc[mt][nt][3] + bb.y);
            if (act) {
                v0.x = fmaxf(v0.x, 0.0f); v0.y = fmaxf(v0.y, 0.0f);
                v1.x = fmaxf(v1.x, 0.0f); v1.y = fmaxf(v1.y, 0.0f);
            }
            *(float2*)(C + (size_t)r0 * 128 + col) = v0;
            *(float2*)(C + (size_t)(r0 + 8) * 128 + col) = v1;
        }
    }
}

// ---------------- plain HMMA GEMM: C = act(A[M,K] @ W + bias) ----------------
__global__ __launch_bounds__(256, 3)
void hmma_gemm_kernel(const float* __restrict__ A, const unsigned short* __restrict__ WT,
                      const float* __restrict__ bias, float* __restrict__ C, int K, int act) {
    GEMM_DECLS
    const unsigned short* WH = WT;
    const unsigned short* WL = WT + (size_t)128 * K;
    int nchunk = K >> 6;
    for (int c = 0; c < nchunk; c++) {
        __syncthreads();
        load_A_chunk(A, row0, K, c << 6, sAh, sAl, tid);
        load_B_chunk(WH, WL, K, c << 6, sBh, sBl, tid);
        __syncthreads();
        compute_chunk(sAh, sAl, sBh, sBl, mrow0, ncol0, tq, tr, acc);
    }
    gemm_epilogue(acc, bias, C, row0, mrow0, ncol0, tq, tr, act);
}

// ---------------- gather-fused fe1 GEMM (K=256) ----------------
__global__ __launch_bounds__(256, 3)
void hmma_gemm_gather_kernel(const float* __restrict__ tabA, const int* __restrict__ idxA,
                             const float* __restrict__ tabB, const int* __restrict__ idxB,
                             const unsigned short* __restrict__ WT,
                             const float* __restrict__ bias, float* __restrict__ C) {
    GEMM_DECLS
    const int K = 256;
    const unsigned short* WH = WT;
    const unsigned short* WL = WT + (size_t)128 * K;
    for (int c = 0; c < 4; c++) {
        __syncthreads();
        const float* tab = (c < 2) ? tabA : tabB;
        const int*   idp = (c < 2) ? idxA : idxB;
        int kbase = (c & 1) << 6;
        #pragma unroll
        for (int i = 0; i < 4; i++) {
            int idx = tid + (i << 8);
            int r = idx >> 4;
            int q = idx & 15;
            int gr = idp[row0 + r];
            float4 v = *(const float4*)(tab + (size_t)gr * 128 + kbase + q * 4);
            split_store(v, sAh, sAl, r * 144 + q * 8);
            // prefetch future chunks (one thread per 128B line)
            if (c == 0 && (q & 7) == 0) {
                int grB = idxB[row0 + r];
                prefetchL2(tabA + (size_t)gr  * 128 + 64 + q * 4);   // chunk 1
                prefetchL2(tabB + (size_t)grB * 128 +  0 + q * 4);   // chunk 2
                prefetchL2(tabB + (size_t)grB * 128 + 64 + q * 4);   // chunk 3
            }
        }
        load_B_chunk(WH, WL, K, c << 6, sBh, sBl, tid);
        __syncthreads();
        compute_chunk(sAh, sAl, sBh, sBl, mrow0, ncol0, tq, tr, acc);
    }
    gemm_epilogue(acc, bias, C, row0, mrow0, ncol0, tq, tr, 1);
}

// ---------------- combined prep (all 3 edge sets) ----------------
__global__ void prep_all_kernel(const int* __restrict__ e0, const int* __restrict__ e1,
                                const int* __restrict__ e2) {
    int b = blockIdx.x;
    int slot = blockIdx.y;
    const int* edges = (slot == 0) ? e0 : (slot == 1) ? e1 : e2;
    const int* src = edges + (size_t)b*2*EE;
    const int* dst = src + EE;
    __shared__ int   cnt[NN];
    __shared__ float sdinv[NN];
    __shared__ int   base[NN+1];
    int t = threadIdx.x, nt = blockDim.x;

    for (int n = t; n < NN; n += nt) cnt[n] = 0;
    __syncthreads();
    for (int e = t; e < EE; e += nt) atomicAdd(&cnt[dst[e]], 1);
    __syncthreads();
    for (int n = t; n < NN; n += nt) {
        float d = (float)(cnt[n] + 1);
        float di = rsqrtf(d);
        sdinv[n] = di;
        g_dinv[slot*MM + b*NN + n] = di;
    }
    __syncthreads();
    if (t == 0) {
        int s = 0;
        for (int n = 0; n < NN; n++) { base[n] = s; s += cnt[n]; }
        base[NN] = s;
    }
    __syncthreads();
    for (int n = t; n <= NN; n += nt)
        g_offs[(slot*BB + b)*(NN+1) + n] = base[n];
    for (int n = t; n < NN; n += nt) cnt[n] = 0;
    __syncthreads();
    int* osrc = g_ssrc + (slot*BB + b)*EE;
    float* onm = g_snorm + (slot*BB + b)*EE;
    for (int e = t; e < EE; e += nt) {
        int d = dst[e], s = src[e];
        int p = base[d] + atomicAdd(&cnt[d], 1);
        osrc[p] = s;
        onm[p]  = sdinv[s] * sdinv[d];
    }
}

// ---------------- GCN aggregation via CSR gather (positive branch only) ----------------
__global__ void agg_kernel(const float* __restrict__ h,
                           const float* __restrict__ bias,
                           float* __restrict__ outbuf, int relu, int nwarp) {
    int gw   = (blockIdx.x * blockDim.x + threadIdx.x) >> 5;
    int lane = threadIdx.x & 31;
    if (gw >= nwarp) return;
    int b = gw >> 9;
    int n = gw & (NN-1);
    const float* dinv  = g_dinv + b*NN;
    const int*   offs  = g_offs + b*(NN+1);
    const int*   ssrc  = g_ssrc + b*EE;
    const float* snorm = g_snorm + b*EE;
    const float* hb = h + (size_t)b*NN*128;

    float di = dinv[n];
    float4 hv = *(const float4*)(hb + (size_t)n*128 + lane*4);
    float self = di*di;
    float4 acc = make_float4(hv.x*self, hv.y*self, hv.z*self, hv.w*self);

    int beg = offs[n], end = offs[n+1];
    int j = beg;
    for (; j + 1 < end; j += 2) {
        int   s0 = ssrc[j],     s1 = ssrc[j+1];
        float n0 = snorm[j],    n1 = snorm[j+1];
        float4 v0 = *(const float4*)(hb + (size_t)s0*128 + lane*4);
        float4 v1 = *(const float4*)(hb + (size_t)s1*128 + lane*4);
        acc.x += v0.x*n0; acc.y += v0.y*n0; acc.z += v0.z*n0; acc.w += v0.w*n0;
        acc.x += v1.x*n1; acc.y += v1.y*n1; acc.z += v1.z*n1; acc.w += v1.w*n1;
    }
    if (j < end) {
        int   s  = ssrc[j];
        float nm = snorm[j];
        float4 v = *(const float4*)(hb + (size_t)s*128 + lane*4);
        acc.x += v.x*nm; acc.y += v.y*nm; acc.z += v.z*nm; acc.w += v.w*nm;
    }
    float4 bb = make_float4(0.f,0.f,0.f,0.f);
    if (bias) bb = *(const float4*)(bias + lane*4);
    float4 o = make_float4(acc.x+bb.x, acc.y+bb.y, acc.z+bb.z, acc.w+bb.w);
    if (relu) {
        o.x = fmaxf(o.x,0.f); o.y = fmaxf(o.y,0.f);
        o.z = fmaxf(o.z,0.f); o.w = fmaxf(o.w,0.f);
    }
    *(float4*)(outbuf + (size_t)gw*128 + lane*4) = o;
}

// ---------------- fused mal two-level root ----------------
__global__ void malroot_kernel(const float* __restrict__ Hb, const float* __restrict__ g1b,
                               const float* __restrict__ g2W, const float* __restrict__ g2b,
                               const int* __restrict__ root_idx) {
    int gi = blockIdx.x;            // 0..127 (0-63: slot1, 64-127: slot2)
    int slot = 1 + (gi >> 6);
    int b = gi & 63;
    int t = threadIdx.x;            // 128
    int r = root_idx[b];
    const float* dinv  = g_dinv + slot*MM + b*NN;
    const int*   offs  = g_offs + (slot*BB + b)*(NN+1);
    const int*   ssrc  = g_ssrc + (slot*BB + b)*EE;
    const float* snorm = g_snorm + (slot*BB + b)*EE;
    const float* hb = Hb + (size_t)gi*NN*128;
    float bias1 = g1b[t];

    __shared__ float xs[128];
    float xacc = 0.0f;
    int beg = offs[r], end = offs[r+1];
    for (int e = -1; e < end - beg; e++) {
        int s;
        float w;
        if (e < 0) { s = r; float dr = dinv[r]; w = dr * dr; }
        else       { s = ssrc[beg + e]; w = snorm[beg + e]; }
        float ds = dinv[s];
        float a = ds * ds * hb[(size_t)s*128 + t];
        int b2 = offs[s], e2 = offs[s+1];
        for (int j = b2; j < e2; j++)
            a += snorm[j] * hb[(size_t)ssrc[j]*128 + t];
        xacc += fmaxf(a + bias1, 0.0f) * w;
    }
    xs[t] = xacc;
    __syncthreads();

    float o = g2b[t];
    #pragma unroll 8
    for (int k = 0; k < 128; k++)
        o += xs[k] * g2W[k*128 + t];
    g_roots[(size_t)(slot*BB + b)*HH + t] = o;
}

// ---------------- score heads (pos root read directly from Pos) ----------------
__global__ void score_kernel(const float* __restrict__ Pos, const int* __restrict__ root_idx,
                             const float* __restrict__ W1a, const float* __restrict__ b1a,
                             const float* __restrict__ W2a, const float* __restrict__ b2a,
                             const float* __restrict__ W1b, const float* __restrict__ b1b,
                             const float* __restrict__ W2b, const float* __restrict__ b2b,
                             float* __restrict__ out) {
    int combo = blockIdx.x;
    int b     = blockIdx.y;
    int t     = threadIdx.x;
    int rs = (combo < 2) ? 0 : (combo - 1);
    int ms = combo & 1;
    const float* W1 = ms ? W1b : W1a;
    const float* b1 = ms ? b1b : b1a;
    const float* W2 = ms ? W2b : W2a;
    const float* b2 = ms ? b2b : b2a;

    __shared__ float r[128];
    if (rs == 0) {
        int ri = root_idx[b];
        r[t] = Pos[((size_t)b*NN + ri)*128 + t];
    } else {
        r[t] = g_roots[(size_t)(rs*BB + b)*HH + t];
    }
    __syncthreads();

    float hsum = b1[t];
    #pragma unroll 8
    for (int k = 0; k < 128; k++) hsum += r[k] * W1[k*128 + t];
    hsum = fmaxf(hsum, 0.f);
    float p = hsum * W2[t];

    int lane = t & 31, warp = t >> 5;
    #pragma unroll
    for (int off = 16; off; off >>= 1) p += __shfl_down_sync(0xffffffff, p, off);
    __shared__ float ws[4];
    if (lane == 0) ws[warp] = p;
    __syncthreads();
    if (t == 0) {
        float s = ws[0] + ws[1] + ws[2] + ws[3] + b2[0];
        out[combo*BB + b] = 1.f / (1.f + expf(-s));
    }
}

// ---------------- host orchestration ----------------
extern "C" void kernel_launch(void* const* d_in, const int* in_sizes, int n_in,
                              void* d_out, int out_size) {
    const int* node_ids    = (const int*)d_in[0];
    const int* edge_pos    = (const int*)d_in[1];
    const int* root_idx    = (const int*)d_in[2];
    const int* mal_nodes1  = (const int*)d_in[3];
    const int* mal_posidx1 = (const int*)d_in[4];
    const int* edge_m1     = (const int*)d_in[5];
    const int* mal_nodes2  = (const int*)d_in[6];
    const int* mal_posidx2 = (const int*)d_in[7];
    const int* edge_m2     = (const int*)d_in[8];
    const float* embeddings = (const float*)d_in[9];
    const float* features   = (const float*)d_in[10];
    const float* fe_W1 = (const float*)d_in[11];
    const float* fe_b1 = (const float*)d_in[12];
    const float* fe_W2 = (const float*)d_in[13];
    const float* fe_b2 = (const float*)d_in[14];
    const float* g1_W  = (const float*)d_in[15];
    const float* g1_b  = (const float*)d_in[16];
    const float* g2_W  = (const float*)d_in[17];
    const float* g2_b  = (const float*)d_in[18];
    const float* mlp_W1  = (const float*)d_in[19];
    const float* mlp_b1  = (const float*)d_in[20];
    const float* mlp_W2  = (const float*)d_in[21];
    const float* mlp_b2  = (const float*)d_in[22];
    const float* mlp1_W1 = (const float*)d_in[23];
    const float* mlp1_b1 = (const float*)d_in[24];
    const float* mlp1_W2 = (const float*)d_in[25];
    const float* mlp1_b2 = (const float*)d_in[26];
    float* out = (float*)d_out;

    float *X1, *Hb, *Pos, *BF;
    int *MA, *MB;
    unsigned short* WT;
    cudaGetSymbolAddress((void**)&X1,  g_X1);
    cudaGetSymbolAddress((void**)&Hb,  g_Hb);
    cudaGetSymbolAddress((void**)&Pos, g_pos);
    cudaGetSymbolAddress((void**)&BF,  g_bfuse);
    cudaGetSymbolAddress((void**)&MA,  g_midxA);
    cudaGetSymbolAddress((void**)&MB,  g_midxB);
    cudaGetSymbolAddress((void**)&WT,  g_wt);

    unsigned short* wt_fe1 = WT;
    unsigned short* wt_fg  = WT + 65536;
    unsigned short* wt_g2  = WT + 98304;

    const int SMEMSZ = 55296;
    cudaFuncSetAttribute(hmma_gemm_kernel,
                         cudaFuncAttributeMaxDynamicSharedMemorySize, SMEMSZ);
    cudaFuncSetAttribute(hmma_gemm_gather_kernel,
                         cudaFuncAttributeMaxDynamicSharedMemorySize, SMEMSZ);

    const int G1  = MM  / 64;            // 512 gemm blocks
    const int G2  = MM2 / 64;            // 1024
    const int A1  = MM / 8;

    // ---- prep ----
    wprep_all_kernel<<<256, 256>>>(fe_W1, fe_W2, fe_b2, g1_W, g2_W);
    prep_all_kernel<<<dim3(BB, 3), 256>>>(edge_pos, edge_m1, edge_m2);
    midx_kernel<<<MM2/256, 256>>>(mal_posidx1, mal_nodes1, mal_posidx2, mal_nodes2);

    // ---- positive branch ----
    hmma_gemm_gather_kernel<<<G1, 256, SMEMSZ>>>(embeddings, node_ids, features, node_ids,
                                                 wt_fe1, fe_b1, X1);
    hmma_gemm_kernel<<<G1, 256, SMEMSZ>>>(X1, wt_fg, BF, Hb, 128, 0);   // fe2∘g1 fused
    agg_kernel <<<A1, 256>>>(Hb, g1_b, X1, 1, MM);
    hmma_gemm_kernel<<<G1, 256, SMEMSZ>>>(X1, wt_g2, 0, Hb, 128, 0);
    agg_kernel <<<A1, 256>>>(Hb, g2_b, Pos, 0, MM);

    // ---- merged malicious branches ----
    hmma_gemm_gather_kernel<<<G2, 256, SMEMSZ>>>(Pos, MA, features, MB,
                                                 wt_fe1, fe_b1, X1);
    hmma_gemm_kernel<<<G2, 256, SMEMSZ>>>(X1, wt_fg, BF, Hb, 128, 0);   // fe2∘g1 fused
    malroot_kernel<<<128, 128>>>(Hb, g1_b, g2_W, g2_b, root_idx);

    // ---- score heads ----
    score_kernel<<<dim3(4, BB), 128>>>(Pos, root_idx,
                                       mlp_W1, mlp_b1, mlp_W2, mlp_b2,
                                       mlp1_W1, mlp1_b1, mlp1_W2, mlp1_b2, out);
    (void)in_sizes; (void)n_in; (void)out_size;
}

// round 15
// speedup vs baseline: 1.0672x; 1.0672x over previous
#include <cuda_runtime.h>
#include <cuda_bf16.h>
#include <cstdint>
#include <math.h>

#define BB 64
#define NN 512
#define EE 8192
#define HH 128
#define MM (BB*NN)   // 32768
#define MM2 (2*MM)

// ---------------- scratch (static device allocations) ----------------
__device__ float g_X1 [(size_t)MM2*128];
__device__ float g_Hb [(size_t)MM2*128];
__device__ float g_pos[(size_t)MM*128];
__device__ float g_dinv [3*MM];
__device__ int   g_offs [3*BB*(NN+1)];
__device__ int   g_ssrc [3*BB*EE];
__device__ float g_snorm[3*BB*EE];
__device__ float g_roots[3*BB*HH];       // slots 1,2 used (mal); pos read direct
__device__ float g_bfuse[128];           // fe_b2 @ g1_W
__device__ int   g_midxA[MM2];           // mal: global row into g_pos
__device__ int   g_midxB[MM2];           // mal: global row into features
// pre-split, pre-transposed weights: fe1 @0 (64K), fused @65536 (32K), g2 @98304 (32K)
__device__ unsigned short g_wt[131072];

// ---------------- helpers ----------------
__device__ __forceinline__ unsigned short bfh(float x) {
    return __bfloat16_as_ushort(__float2bfloat16(x));
}

__device__ __forceinline__ uint32_t s2u(const void* p) {
    uint32_t a;
    asm("{ .reg .u64 t; cvta.to.shared.u64 t, %1; cvt.u32.u64 %0, t; }" : "=r"(a) : "l"(p));
    return a;
}

// mma.sync m16n8k16 row.col f32.bf16.bf16.f32, D += A*B
__device__ __forceinline__ void mma16816(float* d, const uint32_t* a, uint32_t b0, uint32_t b1) {
    asm volatile(
        "mma.sync.aligned.m16n8k16.row.col.f32.bf16.bf16.f32 "
        "{%0,%1,%2,%3}, {%4,%5,%6,%7}, {%8,%9}, {%0,%1,%2,%3};"
        : "+f"(d[0]), "+f"(d[1]), "+f"(d[2]), "+f"(d[3])
        : "r"(a[0]), "r"(a[1]), "r"(a[2]), "r"(a[3]), "r"(b0), "r"(b1));
}

__device__ __forceinline__ void ldsm4(uint32_t* r, uint32_t addr) {
    asm volatile("ldmatrix.sync.aligned.m8n8.x4.shared.b16 {%0,%1,%2,%3}, [%4];"
        : "=r"(r[0]), "=r"(r[1]), "=r"(r[2]), "=r"(r[3]) : "r"(addr));
}

__device__ __forceinline__ void prefetchL2(const void* p) {
    asm volatile("prefetch.global.L2 [%0];" :: "l"(p));
}

// ---------------- combined weight prep (fused weight computed inline) ----------------
__global__ void wprep_all_kernel(const float* __restrict__ fe_W1,
                                 const float* __restrict__ W2, const float* __restrict__ b2,
                                 const float* __restrict__ G1,
                                 const float* __restrict__ g2W) {
    int bid = blockIdx.x;
    int t = threadIdx.x;
    unsigned short* dst;
    int K, idx;
    float x;
    if (bid < 128) {
        dst = g_wt; K = 256; idx = bid*256 + t;
        int k = idx >> 7, n = idx & 127;
        x = fe_W1[(size_t)k * 128 + n];
    } else if (bid < 192) {
        dst = g_wt + 65536; K = 128; idx = (bid-128)*256 + t;
        int k = idx >> 7, n = idx & 127;
        float acc = 0.0f;
        #pragma unroll 8
        for (int m = 0; m < 128; m++) acc += W2[k*128 + m] * G1[m*128 + n];
        x = acc;
        if (bid == 128 && t < 128) {
            float bacc = 0.0f;
            #pragma unroll 8
            for (int m = 0; m < 128; m++) bacc += b2[m] * G1[m*128 + t];
            g_bfuse[t] = bacc;
        }
    } else {
        dst = g_wt + 98304; K = 128; idx = (bid-192)*256 + t;
        int k = idx >> 7, n = idx & 127;
        x = g2W[(size_t)k * 128 + n];
    }
    int k = idx >> 7;
    int n = idx & 127;
    __nv_bfloat16 bh = __float2bfloat16(x);
    float rem = x - __bfloat162float(bh);
    dst[(size_t)n * K + k] = __bfloat16_as_ushort(bh);
    dst[(size_t)128 * K + (size_t)n * K + k] = bfh(rem);
}

// ---------------- mal index flatten ----------------
__global__ void midx_kernel(const int* __restrict__ posidx1, const int* __restrict__ nodes1,
                            const int* __restrict__ posidx2, const int* __restrict__ nodes2) {
    int t = blockIdx.x * 256 + threadIdx.x;
    if (t >= MM2) return;
    int half = t >= MM;
    int r = t & (MM-1);
    int b = r >> 9;
    g_midxA[t] = b * NN + (half ? posidx2[r] : posidx1[r]);
    g_midxB[t] = half ? nodes2[r] : nodes1[r];
}

// ======== GEMM core (M=128 x N=128 tile, 8 warps 4m x 2n, warp tile 32x64) ========
// smem: sAh @0 (18432), sAl @18432, sBh @36864, sBl @55296 -> 73728 B

#define GEMM_DECLS \
    extern __shared__ char smem[]; \
    char* sAh = smem; \
    char* sAl = smem + 18432; \
    char* sBh = smem + 36864; \
    char* sBl = smem + 55296; \
    uint32_t uAh = s2u(sAh); \
    uint32_t uAl = s2u(sAl); \
    uint32_t uBh = s2u(sBh); \
    uint32_t uBl = s2u(sBl); \
    int tid  = threadIdx.x; \
    int lane = tid & 31; \
    int wid  = tid >> 5; \
    int row0 = blockIdx.x * 128; \
    int mrow0 = (wid & 3) * 32; \
    int ncol0 = (wid >> 2) * 64; \
    int tq = lane >> 2; \
    int tr = lane & 3; \
    (void)tq; (void)tr; \
    float acc[2][8][4]; \
    _Pragma("unroll") \
    for (int mt = 0; mt < 2; mt++) \
        _Pragma("unroll") \
        for (int nt = 0; nt < 8; nt++) \
            _Pragma("unroll") \
            for (int i = 0; i < 4; i++) acc[mt][nt][i] = 0.0f;

__device__ __forceinline__ void split_store(float4 v, char* sAh, char* sAl, int off) {
    unsigned short h0 = bfh(v.x), h1 = bfh(v.y), h2 = bfh(v.z), h3 = bfh(v.w);
    float l0 = v.x - __bfloat162float(__ushort_as_bfloat16(h0));
    float l1 = v.y - __bfloat162float(__ushort_as_bfloat16(h1));
    float l2 = v.z - __bfloat162float(__ushort_as_bfloat16(h2));
    float l3 = v.w - __bfloat162float(__ushort_as_bfloat16(h3));
    uint2 hv = make_uint2((uint32_t)h0 | ((uint32_t)h1 << 16),
                          (uint32_t)h2 | ((uint32_t)h3 << 16));
    uint2 lv = make_uint2((uint32_t)bfh(l0) | ((uint32_t)bfh(l1) << 16),
                          (uint32_t)bfh(l2) | ((uint32_t)bfh(l3) << 16));
    *(uint2*)(sAh + off) = hv;
    *(uint2*)(sAl + off) = lv;
}

__device__ __forceinline__ void load_B_chunk(const unsigned short* WH, const unsigned short* WL,
                                             int K, int k0, char* sBh, char* sBl, int tid) {
    #pragma unroll
    for (int i = 0; i < 4; i++) {
        int idx = tid + (i << 8);
        int n = idx >> 3;
        int q = idx & 7;
        size_t goff = (size_t)n * K + k0 + q * 8;
        *(uint4*)(sBh + n * 144 + q * 16) = *(const uint4*)(WH + goff);
        *(uint4*)(sBl + n * 144 + q * 16) = *(const uint4*)(WL + goff);
    }
}

// fragment compute via ldmatrix: per ks, A = 2x2 ldsm4, B = 4x2 ldsm4
__device__ __forceinline__ void compute_chunk(uint32_t uAh, uint32_t uAl,
                                              uint32_t uBh, uint32_t uBl,
                                              int mrow0, int ncol0, int lane,
                                              float acc[2][8][4]) {
    int m8 = lane >> 3;             // 0..3 (matrix select)
    int r8 = lane & 7;              // row within matrix
    int a_row = (m8 & 1) * 8 + r8;  // A: m1/m3 -> +8 rows
    int a_col = (m8 >> 1) * 16;     // A: m2/m3 -> +8 k (16 bytes)
    int b_row = (m8 >> 1) * 8 + r8; // B: m2/m3 -> +8 n
    int b_col = (m8 & 1) * 16;      // B: m1/m3 -> +8 k
    #pragma unroll
    for (int ks = 0; ks < 4; ks++) {
        uint32_t ah[2][4], al[2][4];
        #pragma unroll
        for (int mt = 0; mt < 2; mt++) {
            uint32_t ad = (uint32_t)((mrow0 + mt * 16 + a_row) * 144 + ks * 32 + a_col);
            ldsm4(ah[mt], uAh + ad);
            ldsm4(al[mt], uAl + ad);
        }
        #pragma unroll
        for (int ntp = 0; ntp < 4; ntp++) {
            uint32_t bd = (uint32_t)((ncol0 + ntp * 16 + b_row) * 144 + ks * 32 + b_col);
            uint32_t bh[4], bl[4];
            ldsm4(bh, uBh + bd);
            ldsm4(bl, uBl + bd);
            #pragma unroll
            for (int h = 0; h < 2; h++) {
                int nt = ntp * 2 + h;
                #pragma unroll
                for (int mt = 0; mt < 2; mt++) {
                    mma16816(acc[mt][nt], ah[mt], bh[h*2], bh[h*2+1]);   // hi*hi
                    mma16816(acc[mt][nt], al[mt], bh[h*2], bh[h*2+1]);   // lo*hi
                    mma16816(acc[mt][nt], ah[mt], bl[h*2], bl[h*2+1]);   // hi*lo
                }
            }
        }
    }
}

__device__ __forceinline__ void gemm_epilogue(float acc[2][8][4], const float* bias,
                                              float* C, int row0, int mrow0, int ncol0,
                                              int tq, int tr, int act) {
    #pragma unroll
    for (int nt = 0; nt < 8; nt++) {
        int col = ncol0 + nt * 8 + tr * 2;
        float2 bb = make_float2(0.0f, 0.0f);
        if (bias) bb = *(const float2*)(bias + col);
        #pragma unroll
        for (int mt = 0; mt < 2; mt++) {
            int r0 = row0 + mrow0 + mt * 16 + tq;
            float2 v0 = make_float2(acc[mt][nt][0] + bb.x, acc[mt][nt][1] + bb.y);
            float2 v1 = make_float2(acc[mt][nt][2] + bb.x, acc[mt][nt][3] + bb.y);
            if (act) {
                v0.x = fmaxf(v0.x, 0.0f); v0.y = fmaxf(v0.y, 0.0f);
                v1.x = fmaxf(v1.x, 0.0f); v1.y = fmaxf(v1.y, 0.0f);
            }
            *(float2*)(C + (size_t)r0 * 128 + col) = v0;
            *(float2*)(C + (size_t)(r0 + 8) * 128 + col) = v1;
        }
    }
}

// ---------------- plain HMMA GEMM: C = act(A[M,K] @ W + bias) ----------------
__global__ __launch_bounds__(256, 2)
void hmma_gemm_kernel(const float* __restrict__ A, const unsigned short* __restrict__ WT,
                      const float* __restrict__ bias, float* __restrict__ C, int K, int act) {
    GEMM_DECLS
    const unsigned short* WH = WT;
    const unsigned short* WL = WT + (size_t)128 * K;
    int nchunk = K >> 6;
    for (int c = 0; c < nchunk; c++) {
        __syncthreads();
        #pragma unroll
        for (int i = 0; i < 8; i++) {
            int idx = tid + (i << 8);
            int r = idx >> 4;
            int q = idx & 15;
            float4 v = *(const float4*)(A + (size_t)(row0 + r) * K + (c << 6) + q * 4);
            split_store(v, sAh, sAl, r * 144 + q * 8);
        }
        load_B_chunk(WH, WL, K, c << 6, sBh, sBl, tid);
        __syncthreads();
        compute_chunk(uAh, uAl, uBh, uBl, mrow0, ncol0, lane, acc);
    }
    gemm_epilogue(acc, bias, C, row0, mrow0, ncol0, tq, tr, act);
}

// ---------------- gather-fused fe1 GEMM (K=256) ----------------
__global__ __launch_bounds__(256, 2)
void hmma_gemm_gather_kernel(const float* __restrict__ tabA, const int* __restrict__ idxA,
                             const float* __restrict__ tabB, const int* __restrict__ idxB,
                             const unsigned short* __restrict__ WT,
                             const float* __restrict__ bias, float* __restrict__ C) {
    GEMM_DECLS
    const int K = 256;
    const unsigned short* WH = WT;
    const unsigned short* WL = WT + (size_t)128 * K;
    for (int c = 0; c < 4; c++) {
        __syncthreads();
        const float* tab = (c < 2) ? tabA : tabB;
        const int*   idp = (c < 2) ? idxA : idxB;
        int kbase = (c & 1) << 6;
        #pragma unroll
        for (int i = 0; i < 8; i++) {
            int idx = tid + (i << 8);
            int r = idx >> 4;
            int q = idx & 15;
            int gr = idp[row0 + r];
            float4 v = *(const float4*)(tab + (size_t)gr * 128 + kbase + q * 4);
            split_store(v, sAh, sAl, r * 144 + q * 8);
            // prefetch future chunks (one thread per 128B line)
            if (c == 0 && (q & 7) == 0) {
                int grB = idxB[row0 + r];
                prefetchL2(tabA + (size_t)gr  * 128 + 64 + q * 4);   // chunk 1
                prefetchL2(tabB + (size_t)grB * 128 +  0 + q * 4);   // chunk 2
                prefetchL2(tabB + (size_t)grB * 128 + 64 + q * 4);   // chunk 3
            }
        }
        load_B_chunk(WH, WL, K, c << 6, sBh, sBl, tid);
        __syncthreads();
        compute_chunk(uAh, uAl, uBh, uBl, mrow0, ncol0, lane, acc);
    }
    gemm_epilogue(acc, bias, C, row0, mrow0, ncol0, tq, tr, 1);
}

// ---------------- combined prep (all 3 edge sets) ----------------
__global__ void prep_all_kernel(const int* __restrict__ e0, const int* __restrict__ e1,
                                const int* __restrict__ e2) {
    int b = blockIdx.x;
    int slot = blockIdx.y;
    const int* edges = (slot == 0) ? e0 : (slot == 1) ? e1 : e2;
    const int* src = edges + (size_t)b*2*EE;
    const int* dst = src + EE;
    __shared__ int   cnt[NN];
    __shared__ float sdinv[NN];
    __shared__ int   base[NN+1];
    int t = threadIdx.x, nt = blockDim.x;

    for (int n = t; n < NN; n += nt) cnt[n] = 0;
    __syncthreads();
    for (int e = t; e < EE; e += nt) atomicAdd(&cnt[dst[e]], 1);
    __syncthreads();
    for (int n = t; n < NN; n += nt) {
        float d = (float)(cnt[n] + 1);
        float di = rsqrtf(d);
        sdinv[n] = di;
        g_dinv[slot*MM + b*NN + n] = di;
    }
    __syncthreads();
    if (t == 0) {
        int s = 0;
        for (int n = 0; n < NN; n++) { base[n] = s; s += cnt[n]; }
        base[NN] = s;
    }
    __syncthreads();
    for (int n = t; n <= NN; n += nt)
        g_offs[(slot*BB + b)*(NN+1) + n] = base[n];
    for (int n = t; n < NN; n += nt) cnt[n] = 0;
    __syncthreads();
    int* osrc = g_ssrc + (slot*BB + b)*EE;
    float* onm = g_snorm + (slot*BB + b)*EE;
    for (int e = t; e < EE; e += nt) {
        int d = dst[e], s = src[e];
        int p = base[d] + atomicAdd(&cnt[d], 1);
        osrc[p] = s;
        onm[p]  = sdinv[s] * sdinv[d];
    }
}

// ---------------- GCN aggregation via CSR gather (positive branch only) ----------------
__global__ void agg_kernel(const float* __restrict__ h,
                           const float* __restrict__ bias,
                           float* __restrict__ outbuf, int relu, int nwarp) {
    int gw   = (blockIdx.x * blockDim.x + threadIdx.x) >> 5;
    int lane = threadIdx.x & 31;
    if (gw >= nwarp) return;
    int b = gw >> 9;
    int n = gw & (NN-1);
    const float* dinv  = g_dinv + b*NN;
    const int*   offs  = g_offs + b*(NN+1);
    const int*   ssrc  = g_ssrc + b*EE;
    const float* snorm = g_snorm + b*EE;
    const float* hb = h + (size_t)b*NN*128;

    float di = dinv[n];
    float4 hv = *(const float4*)(hb + (size_t)n*128 + lane*4);
    float self = di*di;
    float4 acc = make_float4(hv.x*self, hv.y*self, hv.z*self, hv.w*self);

    int beg = offs[n], end = offs[n+1];
    int j = beg;
    for (; j + 1 < end; j += 2) {
        int   s0 = ssrc[j],     s1 = ssrc[j+1];
        float n0 = snorm[j],    n1 = snorm[j+1];
        float4 v0 = *(const float4*)(hb + (size_t)s0*128 + lane*4);
        float4 v1 = *(const float4*)(hb + (size_t)s1*128 + lane*4);
        acc.x += v0.x*n0; acc.y += v0.y*n0; acc.z += v0.z*n0; acc.w += v0.w*n0;
        acc.x += v1.x*n1; acc.y += v1.y*n1; acc.z += v1.z*n1; acc.w += v1.w*n1;
    }
    if (j < end) {
        int   s  = ssrc[j];
        float nm = snorm[j];
        float4 v = *(const float4*)(hb + (size_t)s*128 + lane*4);
        acc.x += v.x*nm; acc.y += v.y*nm; acc.z += v.z*nm; acc.w += v.w*nm;
    }
    float4 bb = make_float4(0.f,0.f,0.f,0.f);
    if (bias) bb = *(const float4*)(bias + lane*4);
    float4 o = make_float4(acc.x+bb.x, acc.y+bb.y, acc.z+bb.z, acc.w+bb.w);
    if (relu) {
        o.x = fmaxf(o.x,0.f); o.y = fmaxf(o.y,0.f);
        o.z = fmaxf(o.z,0.f); o.w = fmaxf(o.w,0.f);
    }
    *(float4*)(outbuf + (size_t)gw*128 + lane*4) = o;
}

// ---------------- fused mal two-level root ----------------
__global__ void malroot_kernel(const float* __restrict__ Hb, const float* __restrict__ g1b,
                               const float* __restrict__ g2W, const float* __restrict__ g2b,
                               const int* __restrict__ root_idx) {
    int gi = blockIdx.x;            // 0..127 (0-63: slot1, 64-127: slot2)
    int slot = 1 + (gi >> 6);
    int b = gi & 63;
    int t = threadIdx.x;            // 128
    int r = root_idx[b];
    const float* dinv  = g_dinv + slot*MM + b*NN;
    const int*   offs  = g_offs + (slot*BB + b)*(NN+1);
    const int*   ssrc  = g_ssrc + (slot*BB + b)*EE;
    const float* snorm = g_snorm + (slot*BB + b)*EE;
    const float* hb = Hb + (size_t)gi*NN*128;
    float bias1 = g1b[t];

    __shared__ float xs[128];
    float xacc = 0.0f;
    int beg = offs[r], end = offs[r+1];
    for (int e = -1; e < end - beg; e++) {
        int s;
        float w;
        if (e < 0) { s = r; float dr = dinv[r]; w = dr * dr; }
        else       { s = ssrc[beg + e]; w = snorm[beg + e]; }
        float ds = dinv[s];
        float a = ds * ds * hb[(size_t)s*128 + t];
        int b2 = offs[s], e2 = offs[s+1];
        for (int j = b2; j < e2; j++)
            a += snorm[j] * hb[(size_t)ssrc[j]*128 + t];
        xacc += fmaxf(a + bias1, 0.0f) * w;
    }
    xs[t] = xacc;
    __syncthreads();

    float o = g2b[t];
    #pragma unroll 8
    for (int k = 0; k < 128; k++)
        o += xs[k] * g2W[k*128 + t];
    g_roots[(size_t)(slot*BB + b)*HH + t] = o;
}

// ---------------- score heads (pos root read directly from Pos) ----------------
__global__ void score_kernel(const float* __restrict__ Pos, const int* __restrict__ root_idx,
                             const float* __restrict__ W1a, const float* __restrict__ b1a,
                             const float* __restrict__ W2a, const float* __restrict__ b2a,
                             const float* __restrict__ W1b, const float* __restrict__ b1b,
                             const float* __restrict__ W2b, const float* __restrict__ b2b,
                             float* __restrict__ out) {
    int combo = blockIdx.x;
    int b     = blockIdx.y;
    int t     = threadIdx.x;
    int rs = (combo < 2) ? 0 : (combo - 1);
    int ms = combo & 1;
    const float* W1 = ms ? W1b : W1a;
    const float* b1 = ms ? b1b : b1a;
    const float* W2 = ms ? W2b : W2a;
    const float* b2 = ms ? b2b : b2a;

    __shared__ float r[128];
    if (rs == 0) {
        int ri = root_idx[b];
        r[t] = Pos[((size_t)b*NN + ri)*128 + t];
    } else {
        r[t] = g_roots[(size_t)(rs*BB + b)*HH + t];
    }
    __syncthreads();

    float hsum = b1[t];
    #pragma unroll 8
    for (int k = 0; k < 128; k++) hsum += r[k] * W1[k*128 + t];
    hsum = fmaxf(hsum, 0.f);
    float p = hsum * W2[t];

    int lane = t & 31, warp = t >> 5;
    #pragma unroll
    for (int off = 16; off; off >>= 1) p += __shfl_down_sync(0xffffffff, p, off);
    __shared__ float ws[4];
    if (lane == 0) ws[warp] = p;
    __syncthreads();
    if (t == 0) {
        float s = ws[0] + ws[1] + ws[2] + ws[3] + b2[0];
        out[combo*BB + b] = 1.f / (1.f + expf(-s));
    }
}

// ---------------- host orchestration ----------------
extern "C" void kernel_launch(void* const* d_in, const int* in_sizes, int n_in,
                              void* d_out, int out_size) {
    const int* node_ids    = (const int*)d_in[0];
    const int* edge_pos    = (const int*)d_in[1];
    const int* root_idx    = (const int*)d_in[2];
    const int* mal_nodes1  = (const int*)d_in[3];
    const int* mal_posidx1 = (const int*)d_in[4];
    const int* edge_m1     = (const int*)d_in[5];
    const int* mal_nodes2  = (const int*)d_in[6];
    const int* mal_posidx2 = (const int*)d_in[7];
    const int* edge_m2     = (const int*)d_in[8];
    const float* embeddings = (const float*)d_in[9];
    const float* features   = (const float*)d_in[10];
    const float* fe_W1 = (const float*)d_in[11];
    const float* fe_b1 = (const float*)d_in[12];
    const float* fe_W2 = (const float*)d_in[13];
    const float* fe_b2 = (const float*)d_in[14];
    const float* g1_W  = (const float*)d_in[15];
    const float* g1_b  = (const float*)d_in[16];
    const float* g2_W  = (const float*)d_in[17];
    const float* g2_b  = (const float*)d_in[18];
    const float* mlp_W1  = (const float*)d_in[19];
    const float* mlp_b1  = (const float*)d_in[20];
    const float* mlp_W2  = (const float*)d_in[21];
    const float* mlp_b2  = (const float*)d_in[22];
    const float* mlp1_W1 = (const float*)d_in[23];
    const float* mlp1_b1 = (const float*)d_in[24];
    const float* mlp1_W2 = (const float*)d_in[25];
    const float* mlp1_b2 = (const float*)d_in[26];
    float* out = (float*)d_out;

    float *X1, *Hb, *Pos, *BF;
    int *MA, *MB;
    unsigned short* WT;
    cudaGetSymbolAddress((void**)&X1,  g_X1);
    cudaGetSymbolAddress((void**)&Hb,  g_Hb);
    cudaGetSymbolAddress((void**)&Pos, g_pos);
    cudaGetSymbolAddress((void**)&BF,  g_bfuse);
    cudaGetSymbolAddress((void**)&MA,  g_midxA);
    cudaGetSymbolAddress((void**)&MB,  g_midxB);
    cudaGetSymbolAddress((void**)&WT,  g_wt);

    unsigned short* wt_fe1 = WT;
    unsigned short* wt_fg  = WT + 65536;
    unsigned short* wt_g2  = WT + 98304;

    const int SMEMSZ = 73728;
    cudaFuncSetAttribute(hmma_gemm_kernel,
                         cudaFuncAttributeMaxDynamicSharedMemorySize, SMEMSZ);
    cudaFuncSetAttribute(hmma_gemm_gather_kernel,
                         cudaFuncAttributeMaxDynamicSharedMemorySize, SMEMSZ);

    const int G1  = MM  / 128;           // 256 gemm blocks
    const int G2  = MM2 / 128;           // 512
    const int A1  = MM / 8;

    // ---- prep ----
    wprep_all_kernel<<<256, 256>>>(fe_W1, fe_W2, fe_b2, g1_W, g2_W);
    prep_all_kernel<<<dim3(BB, 3), 256>>>(edge_pos, edge_m1, edge_m2);
    midx_kernel<<<MM2/256, 256>>>(mal_posidx1, mal_nodes1, mal_posidx2, mal_nodes2);

    // ---- positive branch ----
    hmma_gemm_gather_kernel<<<G1, 256, SMEMSZ>>>(embeddings, node_ids, features, node_ids,
                                                 wt_fe1, fe_b1, X1);
    hmma_gemm_kernel<<<G1, 256, SMEMSZ>>>(X1, wt_fg, BF, Hb, 128, 0);   // fe2∘g1 fused
    agg_kernel <<<A1, 256>>>(Hb, g1_b, X1, 1, MM);
    hmma_gemm_kernel<<<G1, 256, SMEMSZ>>>(X1, wt_g2, 0, Hb, 128, 0);
    agg_kernel <<<A1, 256>>>(Hb, g2_b, Pos, 0, MM);

    // ---- merged malicious branches ----
    hmma_gemm_gather_kernel<<<G2, 256, SMEMSZ>>>(Pos, MA, features, MB,
                                                 wt_fe1, fe_b1, X1);
    hmma_gemm_kernel<<<G2, 256, SMEMSZ>>>(X1, wt_fg, BF, Hb, 128, 0);   // fe2∘g1 fused
    malroot_kernel<<<128, 128>>>(Hb, g1_b, g2_W, g2_b, root_idx);

    // ---- score heads ----
    score_kernel<<<dim3(4, BB), 128>>>(Pos, root_idx,
                                       mlp_W1, mlp_b1, mlp_W2, mlp_b2,
                                       mlp1_W1, mlp1_b1, mlp1_W2, mlp1_b2, out);
    (void)in_sizes; (void)n_in; (void)out_size;
}